// round 7
// baseline (speedup 1.0000x reference)
#include <cuda_runtime.h>
#include <cstdint>

#define NC 16
#define HW (512*512)
#define NB 8
#define M (NB*HW)
#define TPX 256
#define NTILES (M / TPX)       // 8192
#define GRID 740               // 148 SMs * 5 CTAs (measured residency)

__device__ double       g_acc[2];
__device__ unsigned int g_done;
__device__ unsigned int g_hdone;
__device__ unsigned int g_ready;
__device__ unsigned int g_tile = GRID;     // work-stealing cursor; reset at end
__device__ float        g_part[GRID * NC];
__device__ float        g_cc[NC];

__device__ __forceinline__ int iget(const int4& v, int j) {
    return j == 0 ? v.x : j == 1 ? v.y : j == 2 ? v.z : v.w;
}
__device__ __forceinline__ void cp16(uint32_t dst, const void* src) {
    asm volatile("cp.async.cg.shared.global [%0], [%1], 16;" :: "r"(dst), "l"(src));
}

__global__ void __launch_bounds__(256) k_all(const float* __restrict__ cls,
                                             const int*   __restrict__ labels,
                                             const float* __restrict__ cums,
                                             float*       __restrict__ out) {
    __shared__ float s_l[2][NC][TPX];     // 32 KB logit tiles
    __shared__ int   s_lab[2][TPX];       //  2 KB label tiles
    __shared__ float smit[NC * NC];       // transposed: smit[c*16+lab]
    __shared__ float sr[256];
    __shared__ int   shist[8 * NC];
    __shared__ int   s_next[2];
    __shared__ bool  s_flag;
    __shared__ float rn[8], rm[8];

    int tid  = threadIdx.x;
    int lane = tid & 31;
    int wrp  = tid >> 5;

    uint32_t s_l_base   = (uint32_t)__cvta_generic_to_shared(&s_l[0][0][0]);
    uint32_t s_lab_base = (uint32_t)__cvta_generic_to_shared(&s_lab[0][0]);
    int ch0  = tid >> 6;                  // 0..3
    int part = tid & 63;

    auto issue = [&](int tile, int bi) {
        int b  = tile >> 10;                       // (tile*256) >> 18
        int hw = (tile & 1023) << 8;               // (tile*256) & (HW-1)
        const float* src = cls + (size_t)b * (NC * HW) + hw + (size_t)ch0 * HW + part * 4;
        uint32_t dst = s_l_base + (uint32_t)(((bi * NC + ch0) * TPX + part * 4) * 4);
        #pragma unroll
        for (int k = 0; k < 4; k++)
            cp16(dst + (uint32_t)k * (4 * TPX * 4), src + (size_t)k * 4 * HW);
        if (tid < 64)
            cp16(s_lab_base + (uint32_t)((bi * TPX + tid * 4) * 4),
                 labels + tile * TPX + tid * 4);
        asm volatile("cp.async.commit_group;");
    };

    // prefetch first tile, steal the second
    issue(blockIdx.x, 0);
    if (tid == 0) s_next[0] = atomicAdd(&g_tile, 1);

    // ---------------- histogram phase (all blocks, overlaps prefetch) --------
    {
        int cnt = 0;
        const int4* lab4 = (const int4*)labels;
        int base = blockIdx.x * 256 + tid;
        #pragma unroll
        for (int k = 0; k < 3; k++) {                       // ceil(524288/189440)=3
            int i = base + k * (GRID * 256);
            int4 lb = (i < M / 4) ? lab4[i] : make_int4(-1, -1, -1, -1);
            #pragma unroll
            for (int j = 0; j < 4; j++) {
                int lab = iget(lb, j);
                #pragma unroll
                for (int c = 0; c < NC; c++) {
                    unsigned mb = __ballot_sync(0xFFFFFFFFu, lab == c);
                    if (lane == c) cnt += __popc(mb);
                }
            }
        }
        if (lane < NC) shist[wrp * NC + lane] = cnt;
        __syncthreads();
        if (tid < NC) {
            int tot = 0;
            #pragma unroll
            for (int i = 0; i < 8; i++) tot += shist[i * NC + tid];
            g_part[blockIdx.x * NC + tid] = (float)tot;
        }
        __threadfence();
        __syncthreads();
        if (tid == 0) s_flag = (atomicAdd(&g_hdone, 1u) == GRID - 1);
        __syncthreads();
        if (s_flag) {                                       // last block reduces
            int c  = tid & 15;
            int r0 = tid >> 4;
            float sum = 0.f;
            for (int k = 0; k < (GRID + 15) / 16; k++) {
                int r = r0 + k * 16;
                if (r < GRID) sum += g_part[r * NC + c];
            }
            sr[tid] = sum;
            __syncthreads();
            if (tid < NC) {
                float tot = 0.f;
                #pragma unroll
                for (int r = 0; r < 16; r++) tot += sr[r * NC + tid];
                g_cc[tid] = fmaxf(cums[tid] + tot, 1.0f);
            }
            __syncthreads();
            if (tid == 0) { g_hdone = 0u; __threadfence(); atomicExch(&g_ready, 1u); }
        }
    }

    // wait for hist result (hist blocks are all resident; spinners nanosleep)
    if (tid == 0) { while (atomicAdd(&g_ready, 0u) == 0u) __nanosleep(64); }
    __syncthreads();
    __threadfence();

    {   // build mitigation table (transposed)
        int labi = tid & 15;
        int ci   = tid >> 4;
        float ratio = g_cc[ci] / g_cc[labi];
        smit[tid] = (ratio < 1.0f) ? __powf(ratio, 0.8f) : 1.0f;
    }

    // ---------------- pipelined main loop with work stealing -----------------
    float nll = 0.f, msk = 0.f;
    int t_cur = blockIdx.x;
    int buf = 0;
    while (t_cur < NTILES) {
        __syncthreads();                       // s_next[buf]+smit visible; buf^1 free
        int t_nxt = s_next[buf];
        if (t_nxt < NTILES) {
            issue(t_nxt, buf ^ 1);
            if (tid == 0) s_next[buf ^ 1] = atomicAdd(&g_tile, 1);
        }
        if (t_nxt < NTILES) asm volatile("cp.async.wait_group 1;");
        else                asm volatile("cp.async.wait_group 0;");
        __syncthreads();                       // buf data ready

        int lab = s_lab[buf][tid];

        float e[NC];
        float s = 0.f;
        #pragma unroll
        for (int c = 0; c < NC; c++) {
            float ec = __expf(s_l[buf][c][tid]);   // conflict-free LDS
            e[c] = ec;
            s += ec;
        }
        float l_lab = s_l[buf][lab][tid];          // dynamic LDS, conflict-free
        float selfE = __expf(l_lab);
        float inv = __fdividef(1.0f, fmaxf(selfE, 0.01f * s));

        float sum2 = 0.f;
        #pragma unroll
        for (int c = 0; c < NC; c++) {
            float t  = fmaxf(e[c] * inv, 1.0f);
            float es = e[c] * smit[(c << 4) + lab];
            sum2 = fmaf(es, t * t, sum2);
        }

        if (lab != 0) {
            nll += __logf(sum2) - l_lab;           // ln(selfE) == l_lab exactly
            msk += 1.f;
        }
        t_cur = t_nxt;
        buf ^= 1;
    }

    // ---------------- block reduction + finalize -----------------------------
    #pragma unroll
    for (int o = 16; o > 0; o >>= 1) {
        nll += __shfl_down_sync(0xFFFFFFFFu, nll, o);
        msk += __shfl_down_sync(0xFFFFFFFFu, msk, o);
    }
    if (lane == 0) { rn[wrp] = nll; rm[wrp] = msk; }
    __syncthreads();
    if (tid == 0) {
        float a = 0.f, bs = 0.f;
        #pragma unroll
        for (int i = 0; i < 8; i++) { a += rn[i]; bs += rm[i]; }
        atomicAdd(&g_acc[0], (double)a);
        atomicAdd(&g_acc[1], (double)bs);
        __threadfence();
        unsigned v = atomicAdd(&g_done, 1u);
        if (v == GRID - 1) {                   // last block: finalize + reset all
            __threadfence();
            out[0] = (float)(g_acc[0] / g_acc[1]);
            g_acc[0] = 0.0;
            g_acc[1] = 0.0;
            g_done   = 0u;
            g_ready  = 0u;
            g_tile   = GRID;
        }
    }
}

extern "C" void kernel_launch(void* const* d_in, const int* in_sizes, int n_in,
                              void* d_out, int out_size) {
    const float* cls    = (const float*)d_in[0];
    const int*   labels = (const int*)  d_in[1];
    const float* cums   = (const float*)d_in[2];
    float* out = (float*)d_out;

    k_all<<<GRID, 256>>>(cls, labels, cums, out);
}

// round 8
// speedup vs baseline: 1.0908x; 1.0908x over previous
#include <cuda_runtime.h>
#include <cstdint>

#define NC 16
#define HW (512*512)
#define NB 8
#define M (NB*HW)
#define HBLK 256
#define TPX 256
#define NTILES (M / TPX)       // 8192
#define GRID 740               // 148 SMs * 5 CTAs (measured residency)

__device__ double       g_acc[2];
__device__ unsigned int g_done;
__device__ unsigned int g_hdone;
__device__ unsigned int g_tile = GRID;     // stealing cursor; reset by last block
__device__ float        g_part[HBLK * NC];
__device__ float        g_cc[NC];

__device__ __forceinline__ int iget(const int4& v, int j) {
    return j == 0 ? v.x : j == 1 ? v.y : j == 2 ? v.z : v.w;
}
__device__ __forceinline__ void cp16(uint32_t dst, const void* src) {
    asm volatile("cp.async.cg.shared.global [%0], [%1], 16;" :: "r"(dst), "l"(src));
}

// ------------------------------------------------ histogram + last-block reduce
__global__ void __launch_bounds__(256) k_hist(const int4* __restrict__ labels,
                                              const float* __restrict__ cums) {
    int lane = threadIdx.x & 31;
    int w    = threadIdx.x >> 5;
    int cnt = 0;
    int idx    = blockIdx.x * blockDim.x + threadIdx.x;
    int stride = gridDim.x * blockDim.x;
    for (int i = idx; i < M / 4; i += stride) {
        int4 lb = labels[i];
        #pragma unroll
        for (int k = 0; k < 4; k++) {
            int lab = iget(lb, k);
            #pragma unroll
            for (int c = 0; c < NC; c++) {
                unsigned mb = __ballot_sync(0xFFFFFFFFu, lab == c);
                if (lane == c) cnt += __popc(mb);
            }
        }
    }
    __shared__ int sm[8 * NC];
    if (lane < NC) sm[w * NC + lane] = cnt;
    __syncthreads();
    int t = threadIdx.x;
    if (t < NC) {
        int tot = 0;
        #pragma unroll
        for (int i = 0; i < 8; i++) tot += sm[i * NC + t];
        g_part[blockIdx.x * NC + t] = (float)tot;
    }
    __shared__ bool is_last;
    __threadfence();
    __syncthreads();
    if (t == 0) is_last = (atomicAdd(&g_hdone, 1u) == HBLK - 1);
    __syncthreads();
    if (is_last) {
        __shared__ float sr[256];
        int c  = t & 15;
        int r0 = t >> 4;
        float sum = 0.f;
        #pragma unroll
        for (int k = 0; k < HBLK / 16; k++)
            sum += g_part[(r0 + k * 16) * NC + c];
        sr[t] = sum;
        __syncthreads();
        if (t < NC) {
            float tot = 0.f;
            #pragma unroll
            for (int r = 0; r < 16; r++) tot += sr[r * NC + t];
            g_cc[t] = fmaxf(cums[t] + tot, 1.0f);
        }
        if (t == 0) g_hdone = 0u;
        __threadfence();
    }
}

// ------------------------------------------------ pipelined main, work stealing
__global__ void __launch_bounds__(256) k_main(const float* __restrict__ cls,
                                              const int*   __restrict__ labels,
                                              float*       __restrict__ out) {
    __shared__ float s_l[2][NC][TPX];     // 32 KB
    __shared__ int   s_lab[2][TPX];       //  2 KB
    __shared__ float smit[NC * NC];       //  1 KB transposed: smit[c*16+lab]
    __shared__ int   s_next[2];
    __shared__ float rn[8], rm[8];

    int tid  = threadIdx.x;
    int lane = tid & 31;
    int wrp  = tid >> 5;
    {
        int labi = tid & 15;
        int ci   = tid >> 4;
        float ratio = g_cc[ci] / g_cc[labi];
        smit[tid] = (ratio < 1.0f) ? __powf(ratio, 0.8f) : 1.0f;
    }

    uint32_t s_l_base   = (uint32_t)__cvta_generic_to_shared(&s_l[0][0][0]);
    uint32_t s_lab_base = (uint32_t)__cvta_generic_to_shared(&s_lab[0][0]);
    int ch0  = tid >> 6;                  // 0..3
    int part = tid & 63;

    auto issue = [&](int tile, int bi) {
        int b  = tile >> 10;                       // (tile*256) >> 18
        int hw = (tile & 1023) << 8;
        const float* src = cls + (size_t)b * (NC * HW) + hw + (size_t)ch0 * HW + part * 4;
        uint32_t dst = s_l_base + (uint32_t)(((bi * NC + ch0) * TPX + part * 4) * 4);
        #pragma unroll
        for (int k = 0; k < 4; k++)
            cp16(dst + (uint32_t)k * (4 * TPX * 4), src + (size_t)k * 4 * HW);
        if (tid < 64)
            cp16(s_lab_base + (uint32_t)((bi * TPX + tid * 4) * 4),
                 labels + tile * TPX + tid * 4);
        asm volatile("cp.async.commit_group;");
    };

    // first tile = blockIdx; steal the second
    issue(blockIdx.x, 0);
    if (tid == 0) s_next[0] = atomicAdd(&g_tile, 1);

    float nll = 0.f, msk = 0.f;
    int t_cur = blockIdx.x;
    int buf = 0;
    while (t_cur < NTILES) {
        __syncthreads();                   // s_next[buf] (+smit first pass) visible
        int t_nxt = s_next[buf];
        if (t_nxt < NTILES) {
            issue(t_nxt, buf ^ 1);
            if (tid == 0) s_next[buf ^ 1] = atomicAdd(&g_tile, 1);
            asm volatile("cp.async.wait_group 1;");
        } else {
            asm volatile("cp.async.wait_group 0;");
        }
        __syncthreads();                   // buf data ready

        int lab = s_lab[buf][tid];

        float e[NC];
        float s = 0.f;
        #pragma unroll
        for (int c = 0; c < NC; c++) {
            float ec = __expf(s_l[buf][c][tid]);   // conflict-free LDS
            e[c] = ec;
            s += ec;
        }
        float l_lab = s_l[buf][lab][tid];          // dynamic LDS, conflict-free
        float selfE = __expf(l_lab);
        float inv = __fdividef(1.0f, fmaxf(selfE, 0.01f * s));

        float sum2 = 0.f;
        #pragma unroll
        for (int c = 0; c < NC; c++) {
            float t  = fmaxf(e[c] * inv, 1.0f);
            float es = e[c] * smit[(c << 4) + lab];
            sum2 = fmaf(es, t * t, sum2);
        }

        if (lab != 0) {
            nll += __logf(sum2) - l_lab;           // ln(selfE) == l_lab exactly
            msk += 1.f;
        }
        t_cur = t_nxt;
        buf ^= 1;
    }

    // block reduction + finalize
    #pragma unroll
    for (int o = 16; o > 0; o >>= 1) {
        nll += __shfl_down_sync(0xFFFFFFFFu, nll, o);
        msk += __shfl_down_sync(0xFFFFFFFFu, msk, o);
    }
    if (lane == 0) { rn[wrp] = nll; rm[wrp] = msk; }
    __syncthreads();
    if (tid == 0) {
        float a = 0.f, bs = 0.f;
        #pragma unroll
        for (int i = 0; i < 8; i++) { a += rn[i]; bs += rm[i]; }
        atomicAdd(&g_acc[0], (double)a);
        atomicAdd(&g_acc[1], (double)bs);
        __threadfence();
        unsigned v = atomicAdd(&g_done, 1u);
        if (v == GRID - 1) {               // last block: finalize + reset
            __threadfence();
            out[0] = (float)(g_acc[0] / g_acc[1]);
            g_acc[0] = 0.0;
            g_acc[1] = 0.0;
            g_done   = 0u;
            g_tile   = GRID;
        }
    }
}

extern "C" void kernel_launch(void* const* d_in, const int* in_sizes, int n_in,
                              void* d_out, int out_size) {
    const float* cls    = (const float*)d_in[0];
    const int*   labels = (const int*)  d_in[1];
    const float* cums   = (const float*)d_in[2];
    float* out = (float*)d_out;

    k_hist<<<HBLK, 256>>>((const int4*)labels, cums);
    k_main<<<GRID, 256>>>(cls, labels, out);
}